// round 5
// baseline (speedup 1.0000x reference)
#include <cuda_runtime.h>
#include <cuda_fp16.h>

// Problem constants
#define Bb    256
#define Tt    512
#define DIN   128
#define Hh    256
#define DOUT  64
#define KTOT  384           // DIN + H
#define LEAK  0.01f

// Partitioning of W_ih row along k:
//   k in [0, KREG)      -> fp32 in registers (exact)
//   k in [KREG, KTOT)   -> fp16 in shared memory
#define KREG  160
#define NPAIR (KREG/2)      // 80 packed f32x2 register pairs
#define KSH   (KTOT-KREG)   // 224
#define NGRP  (KSH/8)       // 28 groups of 8 halves

#define SMEM_W_BYTES (NGRP*Hh*8*2)                 // 114688
#define SMEM_BYTES   (SMEM_W_BYTES + 2*KTOT*4)     // + comb buffers = 117760

// W_ho (64x256) in fp16, grouped [j/8][d][8] for coalesced LDG.128; L1-resident.
__device__ __align__(16) __half g_Who[DOUT*Hh];

__global__ void prep_who_kernel(const float* __restrict__ W_ho) {
    int i = blockIdx.x * blockDim.x + threadIdx.x;
    if (i < DOUT*Hh) {
        int d = i / Hh, j = i % Hh;                 // W_ho row-major [d][j]
        g_Who[(j >> 3)*(DOUT*8) + d*8 + (j & 7)] = __float2half_rn(W_ho[i]);
    }
}

// ---- packed fp32x2 helpers (FFMA2 path: only reachable via PTX) ----
__device__ __forceinline__ void ffma2(unsigned long long& acc,
                                      unsigned long long a, unsigned long long b) {
    asm("fma.rn.f32x2 %0, %1, %2, %0;" : "+l"(acc) : "l"(a), "l"(b));
}
__device__ __forceinline__ unsigned long long packf2(float x, float y) {
    unsigned long long r;
    asm("mov.b64 %0, {%1, %2};" : "=l"(r) : "f"(x), "f"(y));
    return r;
}
__device__ __forceinline__ float2 unpackf2(unsigned long long v) {
    float2 r;
    asm("mov.b64 {%0, %1}, %2;" : "=f"(r.x), "=f"(r.y) : "l"(v));
    return r;
}

// Persistent RNN kernel: 128 CTAs x 256 threads, 2 batch rows per CTA,
// loops over all T=512 steps with h resident in smem. Thread t owns h-index t.
__global__ void __launch_bounds__(256, 1)
rnn_persist_kernel(const float* __restrict__ inputs,   // [B, T, DIN]
                   const float* __restrict__ x0,       // [B, DOUT]
                   const float* __restrict__ h0,       // [B, H]
                   const float* __restrict__ W_ih,     // [H, KTOT]
                   const float* __restrict__ b_ih,     // [H]
                   const float* __restrict__ b_ho,     // [DOUT]
                   float* __restrict__ out_x,          // [B, T+1, DOUT]
                   float* __restrict__ out_h)          // [B, T+1, H]
{
    extern __shared__ unsigned char smem_raw[];
    __half* sW    = (__half*)smem_raw;                       // [NGRP][Hh][8] halves
    float*  comb0 = (float*)(smem_raw + SMEM_W_BYTES);       // [KTOT]: u | h, row0
    float*  comb1 = comb0 + KTOT;                            // row1

    const int t    = threadIdx.x;           // h index this thread owns
    const int row0 = (int)blockIdx.x * 2;
    const int row1 = row0 + 1;

    // ---- 1) Register-resident fp32 weights: W_ih[t][0:KREG], packed in pairs ----
    unsigned long long wreg[NPAIR];
    {
        const float2* wr = (const float2*)(W_ih + (size_t)t * KTOT);
        #pragma unroll
        for (int p = 0; p < NPAIR; p++) {
            float2 w = __ldg(&wr[p]);
            wreg[p] = packf2(w.x, w.y);
        }
    }

    // ---- 2) Shared fp16 weights: W_ih[h][KREG:KTOT], layout [ks/8][h][8] ----
    for (int i = t; i < Hh * KSH; i += 256) {
        int h = i / KSH, ks = i % KSH;
        sW[(ks >> 3)*(Hh*8) + h*8 + (ks & 7)] =
            __float2half_rn(W_ih[(size_t)h * KTOT + KREG + ks]);
    }

    // ---- 3) comb init: [u_0 | h0], and t=0 outputs ----
    {
        int lane = t & 127, r = t >> 7;
        const int row = r ? row1 : row0;
        (r ? comb1 : comb0)[lane] = inputs[(size_t)row * Tt * DIN + lane];
    }
    for (int i = t; i < 2*Hh; i += 256) {
        int r = i >> 8, j = i & 255;
        const int row = r ? row1 : row0;
        float v = h0[(size_t)row * Hh + j];
        (r ? comb1 : comb0)[DIN + j] = v;
        out_h[(size_t)row * (Tt+1) * Hh + j] = v;
    }
    if (t < 2*DOUT) {
        int r = t >> 6, d = t & 63;
        const int row = r ? row1 : row0;
        out_x[(size_t)row * (Tt+1) * DOUT + d] = x0[(size_t)row * DOUT + d];
    }

    const float bih = b_ih[t];
    const float bho = (t < 128) ? b_ho[t & 63] : 0.f;

    const float* ub   = inputs + (size_t)((t < 128) ? row0 : row1) * Tt * DIN;
    const int   ulane = t & 127;

    float* hx0 = out_h + (size_t)row0 * (Tt+1) * Hh;
    float* hx1 = out_h + (size_t)row1 * (Tt+1) * Hh;
    float* xb  = (t < 128)
               ? (out_x + (size_t)((t < 64) ? row0 : row1) * (Tt+1) * DOUT)
               : out_x;  // unused when t >= 128

    __syncthreads();

    for (int step = 0; step < Tt; step++) {
        // Prefetch next u into registers early (latency hidden by GEMM1).
        float upref = 0.f;
        if (step + 1 < Tt) upref = __ldg(&ub[(size_t)(step + 1) * DIN + ulane]);

        // ---- GEMM1: pre[r][t] = sum_k W_ih[t][k] * comb[r][k] ----
        unsigned long long acc0 = 0ull, acc1 = 0ull;  // {even-k sum, odd-k sum}

        // fp32 register portion, k in [0, KREG)
        #pragma unroll
        for (int p = 0; p < NPAIR; p += 2) {
            ulonglong2 c0 = *(const ulonglong2*)(comb0 + p*2);   // broadcast LDS
            ulonglong2 c1 = *(const ulonglong2*)(comb1 + p*2);
            ffma2(acc0, wreg[p],   c0.x);
            ffma2(acc0, wreg[p+1], c0.y);
            ffma2(acc1, wreg[p],   c1.x);
            ffma2(acc1, wreg[p+1], c1.y);
        }

        // fp16 shared portion, k in [KREG, KTOT)
        #pragma unroll 4
        for (int g = 0; g < NGRP; g++) {
            uint4 wv = *(const uint4*)(sW + g*(Hh*8) + t*8);     // conflict-free
            ulonglong2 c0a = *(const ulonglong2*)(comb0 + KREG + g*8);
            ulonglong2 c0b = *(const ulonglong2*)(comb0 + KREG + g*8 + 4);
            ulonglong2 c1a = *(const ulonglong2*)(comb1 + KREG + g*8);
            ulonglong2 c1b = *(const ulonglong2*)(comb1 + KREG + g*8 + 4);
            float2 f0 = __half22float2(*(const __half2*)&wv.x);
            float2 f1 = __half22float2(*(const __half2*)&wv.y);
            float2 f2 = __half22float2(*(const __half2*)&wv.z);
            float2 f3 = __half22float2(*(const __half2*)&wv.w);
            unsigned long long w0 = packf2(f0.x, f0.y);
            unsigned long long w1 = packf2(f1.x, f1.y);
            unsigned long long w2 = packf2(f2.x, f2.y);
            unsigned long long w3 = packf2(f3.x, f3.y);
            ffma2(acc0, w0, c0a.x);
            ffma2(acc0, w1, c0a.y);
            ffma2(acc0, w2, c0b.x);
            ffma2(acc0, w3, c0b.y);
            ffma2(acc1, w0, c1a.x);
            ffma2(acc1, w1, c1a.y);
            ffma2(acc1, w2, c1b.x);
            ffma2(acc1, w3, c1b.y);
        }

        float2 s0 = unpackf2(acc0);
        float2 s1 = unpackf2(acc1);
        float pre0 = s0.x + s0.y + bih;
        float pre1 = s1.x + s1.y + bih;
        float hn0 = pre0 > 0.f ? pre0 : LEAK * pre0;
        float hn1 = pre1 > 0.f ? pre1 : LEAK * pre1;

        __syncthreads();   // all reads of old comb done

        comb0[DIN + t] = hn0;
        comb1[DIN + t] = hn1;
        if (step + 1 < Tt) ((t < 128) ? comb0 : comb1)[ulane] = upref;
        hx0[(size_t)(step + 1) * Hh + t] = hn0;
        hx1[(size_t)(step + 1) * Hh + t] = hn1;

        __syncthreads();   // new comb visible

        // ---- GEMM2: x[r][d] = sum_j h_new[r][j] * W_ho[d][j] ----
        // Warps 0..3 only (one light warp per SMSP -> balanced).
        if (t < 128) {
            const int d = t & 63;
            const float* hc = ((t < 64) ? comb0 : comb1) + DIN;
            unsigned long long xacc = 0ull;
            #pragma unroll 4
            for (int g = 0; g < Hh/8; g++) {
                uint4 wv = *(const uint4*)(g_Who + g*(DOUT*8) + d*8);  // L1 hit
                ulonglong2 ca = *(const ulonglong2*)(hc + g*8);
                ulonglong2 cb = *(const ulonglong2*)(hc + g*8 + 4);
                float2 f0 = __half22float2(*(const __half2*)&wv.x);
                float2 f1 = __half22float2(*(const __half2*)&wv.y);
                float2 f2 = __half22float2(*(const __half2*)&wv.z);
                float2 f3 = __half22float2(*(const __half2*)&wv.w);
                ffma2(xacc, packf2(f0.x, f0.y), ca.x);
                ffma2(xacc, packf2(f1.x, f1.y), ca.y);
                ffma2(xacc, packf2(f2.x, f2.y), cb.x);
                ffma2(xacc, packf2(f3.x, f3.y), cb.y);
            }
            float2 sx = unpackf2(xacc);
            xb[(size_t)(step + 1) * DOUT + d] = sx.x + sx.y + bho;
        }
    }
}

extern "C" void kernel_launch(void* const* d_in, const int* in_sizes, int n_in,
                              void* d_out, int out_size) {
    const float* inputs = (const float*)d_in[0];
    const float* x0     = (const float*)d_in[1];
    const float* h0     = (const float*)d_in[2];
    const float* W_ih   = (const float*)d_in[3];
    const float* b_ih   = (const float*)d_in[4];
    const float* W_ho   = (const float*)d_in[5];
    const float* b_ho   = (const float*)d_in[6];

    float* out_x = (float*)d_out;                                  // [B, T+1, DOUT]
    float* out_h = out_x + (size_t)Bb * (Tt + 1) * DOUT;           // [B, T+1, H]

    cudaFuncSetAttribute(rnn_persist_kernel,
                         cudaFuncAttributeMaxDynamicSharedMemorySize,
                         (int)SMEM_BYTES);

    prep_who_kernel<<<(DOUT*Hh + 255)/256, 256>>>(W_ho);
    rnn_persist_kernel<<<Bb/2, 256, SMEM_BYTES>>>(inputs, x0, h0, W_ih, b_ih,
                                                  b_ho, out_x, out_h);
}